// round 13
// baseline (speedup 1.0000x reference)
#include <cuda_runtime.h>
#include <cuda_bf16.h>
#include <math.h>
#include <stdint.h>

#define NROWS 19712   // 256*77
#define SEQ 77
#define BATCH 256
#define DIM 1024
#define EPSF 1e-15f
#define MAXNORM (1.0f - 1e-5f)

#define NCTA 296
#define NTILES_L 1232       // 154 m-tiles x 8 n-tiles per layer
#define NLAYER 6
#define TOT_TILES (NLAYER * NTILES_L)
#define NMT 154

// scratch (no allocations allowed)
__device__ __nv_bfloat16 g_ahi[(size_t)NROWS * DIM];
__device__ __nv_bfloat16 g_alo[(size_t)NROWS * DIM];
__device__ __nv_bfloat16 g_bhi[(size_t)NROWS * DIM];
__device__ __nv_bfloat16 g_blo[(size_t)NROWS * DIM];
__device__ float g_bufF[(size_t)NROWS * DIM];
__device__ __nv_bfloat16 g_whi[(size_t)6 * DIM * DIM];  // transposed [N][K]
__device__ __nv_bfloat16 g_wlo[(size_t)6 * DIM * DIM];
__device__ float g_ss[NROWS];              // per-row sum of squares (fused he)
__device__ unsigned g_cnt[NLAYER * NMT];   // per-(layer, m-block) completion (64 = done)
__device__ int g_tok64;

// ===========================================================================
// PTX helpers (baseline sm_80/90 features only — valid at compute_103)
// ===========================================================================
__device__ __forceinline__ uint32_t smem_u32(const void* p) {
    uint32_t a;
    asm("{ .reg .u64 t; cvta.to.shared.u64 t, %1; cvt.u32.u64 %0, t; }" : "=r"(a) : "l"(p));
    return a;
}
__device__ __forceinline__ void cp_async16(uint32_t dst, const void* src) {
    asm volatile("cp.async.cg.shared.global [%0], [%1], 16;" :: "r"(dst), "l"(src) : "memory");
}
__device__ __forceinline__ void cp_async_arrive(uint32_t mbar) {
    asm volatile("cp.async.mbarrier.arrive.noinc.shared.b64 [%0];" :: "r"(mbar) : "memory");
}
__device__ __forceinline__ void mbar_init(uint32_t mbar, uint32_t cnt) {
    asm volatile("mbarrier.init.shared.b64 [%0], %1;" :: "r"(mbar), "r"(cnt) : "memory");
}
__device__ __forceinline__ void mbar_arrive(uint32_t mbar) {
    asm volatile("mbarrier.arrive.shared.b64 _, [%0];" :: "r"(mbar) : "memory");
}
__device__ __forceinline__ void mbar_wait(uint32_t mbar, uint32_t parity) {
    asm volatile(
        "{\n\t.reg .pred P1;\n\t"
        "LAB_%=:\n\t"
        "mbarrier.try_wait.parity.acquire.cta.shared::cta.b64 P1, [%0], %1, 0x989680;\n\t"
        "@P1 bra.uni DONE_%=;\n\t"
        "bra.uni LAB_%=;\n\t"
        "DONE_%=:\n\t}"
        :: "r"(mbar), "r"(parity) : "memory");
}
__device__ __forceinline__ void ldsm4(uint32_t addr, uint32_t& r0, uint32_t& r1,
                                      uint32_t& r2, uint32_t& r3) {
    asm volatile("ldmatrix.sync.aligned.m8n8.x4.shared.b16 {%0,%1,%2,%3}, [%4];"
                 : "=r"(r0), "=r"(r1), "=r"(r2), "=r"(r3) : "r"(addr));
}
__device__ __forceinline__ void mma_bf16(float& d0, float& d1, float& d2, float& d3,
                                         uint32_t a0, uint32_t a1, uint32_t a2, uint32_t a3,
                                         uint32_t b0, uint32_t b1) {
    asm volatile("mma.sync.aligned.m16n8k16.row.col.f32.bf16.bf16.f32 "
                 "{%0,%1,%2,%3},{%4,%5,%6,%7},{%8,%9},{%0,%1,%2,%3};"
                 : "+f"(d0), "+f"(d1), "+f"(d2), "+f"(d3)
                 : "r"(a0), "r"(a1), "r"(a2), "r"(a3), "r"(b0), "r"(b1));
}
__device__ __forceinline__ void split_bf16(float v, __nv_bfloat16& hi, __nv_bfloat16& lo) {
    hi = __float2bfloat16(v);
    lo = __float2bfloat16(v - __bfloat162float(hi));
}

// ===========================================================================
// Token layout detection + counter zeroing
// ===========================================================================
__global__ void detect_tok_kernel(const unsigned long long* __restrict__ w, int nwords) {
    __shared__ int flag;
    if (threadIdx.x == 0) flag = 0;
    __syncthreads();
    int bad = 0;
    for (int i = threadIdx.x; i < nwords; i += blockDim.x)
        if (w[i] >> 32) { bad = 1; break; }
    if (bad) flag = 1;
    __syncthreads();
    if (threadIdx.x == 0) g_tok64 = flag ? 0 : 1;
    for (int i = threadIdx.x; i < NLAYER * NMT; i += blockDim.x) g_cnt[i] = 0;
}

// ===========================================================================
// Embedding -> hi/lo bf16 split (also zeroes g_ss for this row)
// ===========================================================================
__global__ void embed_kernel(const void* __restrict__ tokens,
                             const float* __restrict__ tok_w,
                             const float* __restrict__ pos_w,
                             __nv_bfloat16* __restrict__ xhi,
                             __nv_bfloat16* __restrict__ xlo,
                             float* __restrict__ ss) {
    int row = blockIdx.x;
    int s = row % SEQ;
    if (threadIdx.x == 0) ss[row] = 0.f;
    long long t;
    if (g_tok64) t = ((const long long*)tokens)[row];
    else         t = (long long)(((const int*)tokens)[row]);
    int i = threadIdx.x;
    float4 a = ((const float4*)(tok_w + (size_t)t * DIM))[i];
    float4 p = ((const float4*)(pos_w + (size_t)s * DIM))[i];
    float v[4] = {a.x + p.x, a.y + p.y, a.z + p.z, a.w + p.w};
    __nv_bfloat16 h[4], l[4];
    #pragma unroll
    for (int q = 0; q < 4; ++q) split_bf16(v[q], h[q], l[q]);
    size_t base = (size_t)row * DIM + i * 4;
    *(uint2*)(xhi + base) = *(uint2*)h;
    *(uint2*)(xlo + base) = *(uint2*)l;
}

// ===========================================================================
// Weight transpose + split
// ===========================================================================
__global__ void wsplit_kernel(const float* __restrict__ mlp_w,
                              const float* __restrict__ gcn_w,
                              __nv_bfloat16* __restrict__ whi,
                              __nv_bfloat16* __restrict__ wlo) {
    __shared__ float t[32][33];
    int mat = blockIdx.z;
    const float* src = (mat < 5) ? mlp_w + (size_t)mat * DIM * DIM
                                 : gcn_w + (size_t)3 * DIM * DIM;
    size_t doff = (size_t)mat * DIM * DIM;
    int n0 = blockIdx.x * 32, k0 = blockIdx.y * 32;
    for (int i = threadIdx.y; i < 32; i += 8)
        t[i][threadIdx.x] = src[(size_t)(k0 + i) * DIM + n0 + threadIdx.x];
    __syncthreads();
    for (int i = threadIdx.y; i < 32; i += 8) {
        float v = t[threadIdx.x][i];
        __nv_bfloat16 h, l;
        split_bf16(v, h, l);
        size_t d = doff + (size_t)(n0 + i) * DIM + k0 + threadIdx.x;
        whi[d] = h; wlo[d] = l;
    }
}

// ===========================================================================
// Persistent fused 6-layer GEMM chain — mbarrier full/empty pipeline.
// 3 stages; full = 256 cp.async-tracked arrivals, empty = 256 consumer
// arrivals. Parities computed arithmetically (stage s has 11/11/10 uses
// per 32-chunk tile). Per-warp dependency publish/wait (count 64), so no
// block-wide barrier in steady state and no cross-tile stage race.
// ===========================================================================
#define STAGES 3
#define NCHUNK 32
#define TILE_BYTES 8192               // 128 rows x 64B
#define STAGE_BYTES (4 * TILE_BYTES)  // 32 KB
#define DSM_BYTES (STAGES * STAGE_BYTES)  // 96 KB

__device__ __forceinline__ int stage_uses(int s) { return (s == 2) ? 10 : 11; }

__global__ __launch_bounds__(256, 2) void mega_gemm_kernel(
    __nv_bfloat16* __restrict__ ahi, __nv_bfloat16* __restrict__ alo,
    __nv_bfloat16* __restrict__ bhi, __nv_bfloat16* __restrict__ blo,
    const __nv_bfloat16* __restrict__ whi, const __nv_bfloat16* __restrict__ wlo,
    const float* __restrict__ mlp_b, float* __restrict__ ssp)
{
    extern __shared__ char dsm_raw[];
    __shared__ __align__(8) unsigned long long mb_full[STAGES], mb_empty[STAGES];
    uint32_t dsm = smem_u32(dsm_raw);
    uint32_t fullb = smem_u32(mb_full);
    uint32_t emptyb = smem_u32(mb_empty);

    int tid = threadIdx.x, wid = tid >> 5, lid = tid & 31;
    int wm = wid & 1, wn = wid >> 1;

    if (tid == 0) {
        #pragma unroll
        for (int s = 0; s < STAGES; ++s) {
            mbar_init(fullb + s * 8, 256);
            mbar_init(emptyb + s * 8, 256);
        }
    }
    __syncthreads();

    // ldmatrix lane addressing (loop-invariant)
    int t8 = lid >> 3, l8 = lid & 7;
    uint32_t sw = (uint32_t)((l8 >> 1) & 3);
    uint32_t a_row = (uint32_t)(wm * 64 + (t8 & 1) * 8 + l8);
    uint32_t b_row = (uint32_t)(wn * 32 + (t8 >> 1) * 8 + l8);
    uint32_t a_c = (uint32_t)(t8 >> 1);
    uint32_t b_c = (uint32_t)(t8 & 1);
    int er = lid >> 2, ec = (lid & 3) * 2;

    int T = 0;
    for (int t = blockIdx.x; t < TOT_TILES; t += NCTA, ++T) {
        int L  = t / NTILES_L;
        int r  = t - L * NTILES_L;
        int mt = r >> 3, nt = r & 7;
        int bm = mt << 7, bn = nt << 7;

        const __nv_bfloat16* Ahi = (L & 1) ? bhi : ahi;
        const __nv_bfloat16* Alo = (L & 1) ? blo : alo;
        __nv_bfloat16* Ohi = (L & 1) ? ahi : bhi;
        __nv_bfloat16* Olo = (L & 1) ? alo : blo;
        const __nv_bfloat16* Bhi = whi + (size_t)L * DIM * DIM;
        const __nv_bfloat16* Blo = wlo + (size_t)L * DIM * DIM;
        const float* bias = (L < 5) ? mlp_b + L * DIM : nullptr;
        int applySilu = (L < 4);
        float* ssAcc = (L == 4) ? ssp : nullptr;
        const float* ssScale = (L == 5) ? ssp : nullptr;

        // ---- per-warp dependency wait (producers publish per-warp: 64 total) ----
        if (L > 0) {
            if (lid == 0) {
                volatile unsigned* f = &g_cnt[(L - 1) * NMT + mt];
                while (*f < 64u) __nanosleep(64);
            }
            __syncwarp();
        }

        float acc[4][4][4];
        #pragma unroll
        for (int i = 0; i < 4; ++i)
            #pragma unroll
            for (int j = 0; j < 4; ++j)
                #pragma unroll
                for (int q = 0; q < 4; ++q) acc[i][j][q] = 0.f;

        // issue chunk j: wait stage-empty (except very first use), 8 cp.async,
        // then cp.async-tracked arrive on the stage's full barrier.
        auto issue = [&](int j) {
            int s = j % 3;
            int n = T * stage_uses(s) + j / 3;
            if (n > 0) mbar_wait(emptyb + s * 8, (unsigned)(n - 1) & 1u);
            int k0 = j * 32;
            uint32_t st = dsm + s * STAGE_BYTES;
            #pragma unroll
            for (int u = 0; u < 8; ++u) {
                int i = tid + u * 256;
                int tt = i >> 9, rr = (i >> 2) & 127, cc = i & 3;
                const __nv_bfloat16* gb;
                if (tt == 0)      gb = Ahi + (size_t)(bm + rr) * DIM;
                else if (tt == 1) gb = Alo + (size_t)(bm + rr) * DIM;
                else if (tt == 2) gb = Bhi + (size_t)(bn + rr) * DIM;
                else              gb = Blo + (size_t)(bn + rr) * DIM;
                uint32_t daddr = st + tt * TILE_BYTES + rr * 64 + (((cc ^ ((rr >> 1) & 3))) * 16);
                cp_async16(daddr, gb + k0 + cc * 8);
            }
            cp_async_arrive(fullb + s * 8);
        };

        issue(0); issue(1);

        for (int j = 0; j < NCHUNK; ++j) {
            if (j + 2 < NCHUNK) issue(j + 2);

            int s = j % 3;
            mbar_wait(fullb + s * 8,
                      (unsigned)(T * stage_uses(s) + j / 3) & 1u);

            uint32_t st = dsm + s * STAGE_BYTES;
            #pragma unroll
            for (int ks = 0; ks < 2; ++ks) {
                uint32_t a_off = ((a_c + ks * 2) ^ sw) * 16;
                uint32_t b_off = ((b_c + ks * 2) ^ sw) * 16;
                uint32_t ah[4][4], al[4][4], bh2[2][4], bl2[2][4];
                // pass-1 operands first (bh, ah), so MMAs start after 6 ldsm
                #pragma unroll
                for (int np = 0; np < 2; ++np) {
                    uint32_t rb = st + 2 * TILE_BYTES + (b_row + np * 16) * 64 + b_off;
                    ldsm4(rb, bh2[np][0], bh2[np][1], bh2[np][2], bh2[np][3]);
                }
                #pragma unroll
                for (int am = 0; am < 4; ++am) {
                    uint32_t ra = st + (a_row + am * 16) * 64 + a_off;
                    ldsm4(ra, ah[am][0], ah[am][1], ah[am][2], ah[am][3]);
                }
                #pragma unroll
                for (int am = 0; am < 4; ++am)
                    #pragma unroll
                    for (int an = 0; an < 4; ++an) {
                        uint32_t* bp = bh2[an >> 1];
                        mma_bf16(acc[am][an][0], acc[am][an][1], acc[am][an][2], acc[am][an][3],
                                 ah[am][0], ah[am][1], ah[am][2], ah[am][3],
                                 bp[(an & 1) * 2], bp[(an & 1) * 2 + 1]);
                    }
                #pragma unroll
                for (int am = 0; am < 4; ++am) {
                    uint32_t ra = st + TILE_BYTES + (a_row + am * 16) * 64 + a_off;
                    ldsm4(ra, al[am][0], al[am][1], al[am][2], al[am][3]);
                }
                #pragma unroll
                for (int am = 0; am < 4; ++am)
                    #pragma unroll
                    for (int an = 0; an < 4; ++an) {
                        uint32_t* bp = bh2[an >> 1];
                        mma_bf16(acc[am][an][0], acc[am][an][1], acc[am][an][2], acc[am][an][3],
                                 al[am][0], al[am][1], al[am][2], al[am][3],
                                 bp[(an & 1) * 2], bp[(an & 1) * 2 + 1]);
                    }
                #pragma unroll
                for (int np = 0; np < 2; ++np) {
                    uint32_t rb = st + 3 * TILE_BYTES + (b_row + np * 16) * 64 + b_off;
                    ldsm4(rb, bl2[np][0], bl2[np][1], bl2[np][2], bl2[np][3]);
                }
                #pragma unroll
                for (int am = 0; am < 4; ++am)
                    #pragma unroll
                    for (int an = 0; an < 4; ++an) {
                        uint32_t* bp = bl2[an >> 1];
                        mma_bf16(acc[am][an][0], acc[am][an][1], acc[am][an][2], acc[am][an][3],
                                 ah[am][0], ah[am][1], ah[am][2], ah[am][3],
                                 bp[(an & 1) * 2], bp[(an & 1) * 2 + 1]);
                    }
            }
            // this thread's reads of stage s are complete (ldsm results in regs)
            mbar_arrive(emptyb + s * 8);
        }

        // ---- epilogue ----
        float2 bv[4];
        #pragma unroll
        for (int an = 0; an < 4; ++an)
            bv[an] = bias ? *(const float2*)(bias + bn + wn * 32 + an * 8 + ec)
                          : make_float2(0.f, 0.f);

        #pragma unroll
        for (int am = 0; am < 4; ++am) {
            #pragma unroll
            for (int h = 0; h < 2; ++h) {
                int row = bm + wm * 64 + am * 16 + er + h * 8;
                float sc = 1.f;
                if (ssScale) {
                    float ssv = __ldg(ssScale + row);
                    float n = fmaxf(sqrtf(ssv), EPSF);
                    sc = atanhf(fminf(tanhf(n), MAXNORM)) / n;
                }
                float sspv = 0.f;
                #pragma unroll
                for (int an = 0; an < 4; ++an) {
                    int col = bn + wn * 32 + an * 8 + ec;
                    float v0 = acc[am][an][h * 2 + 0] + bv[an].x;
                    float v1 = acc[am][an][h * 2 + 1] + bv[an].y;
                    if (applySilu) {
                        v0 = v0 / (1.0f + __expf(-v0));
                        v1 = v1 / (1.0f + __expf(-v1));
                    }
                    if (ssAcc) sspv += v0 * v0 + v1 * v1;
                    v0 *= sc; v1 *= sc;
                    __nv_bfloat16 h0, l0, h1, l1;
                    split_bf16(v0, h0, l0);
                    split_bf16(v1, h1, l1);
                    __nv_bfloat16 hp[2] = {h0, h1}, lp[2] = {l0, l1};
                    *(uint32_t*)(Ohi + (size_t)row * DIM + col) = *(uint32_t*)hp;
                    *(uint32_t*)(Olo + (size_t)row * DIM + col) = *(uint32_t*)lp;
                }
                if (ssAcc) {
                    sspv += __shfl_xor_sync(0xffffffffu, sspv, 1);
                    sspv += __shfl_xor_sync(0xffffffffu, sspv, 2);
                    if ((lid & 3) == 0) atomicAdd(ssAcc + row, sspv);
                }
            }
        }

        // ---- per-warp completion publish ----
        __threadfence();
        if (lid == 0) atomicAdd(&g_cnt[L * NMT + mt], 1u);
    }
}

// ===========================================================================
// block reduction over 256 threads
// ===========================================================================
__device__ __forceinline__ float block_reduce_sum_256(float v) {
    __shared__ float s[8];
    __syncthreads();
    int lane = threadIdx.x & 31, w = threadIdx.x >> 5;
    #pragma unroll
    for (int o = 16; o; o >>= 1) v += __shfl_down_sync(0xffffffffu, v, o);
    if (lane == 0) s[w] = v;
    __syncthreads();
    if (threadIdx.x == 0) {
        float t = 0.f;
        #pragma unroll
        for (int i = 0; i < 8; ++i) t += s[i];
        s[0] = t;
    }
    __syncthreads();
    return s[0];
}

// ===========================================================================
// Tensor-core aggregation: agg[b,c,d] = sum_r adj[r,c]*m[r,d] + bias[d].
// ===========================================================================
#define ASTR 88                               // elements; 176B row stride
#define AGG_SMEM ((80 + 2 * 128) * ASTR * 2)  // 59136 B

__global__ __launch_bounds__(128) void agg_mma_kernel(
    const __nv_bfloat16* __restrict__ mhi, const __nv_bfloat16* __restrict__ mlo,
    const int* __restrict__ edge, const float* __restrict__ bias,
    float* __restrict__ outF)
{
    extern __shared__ char agg_raw[];
    uint32_t sA  = smem_u32(agg_raw);           // adjT [80][88]
    uint32_t sBh = sA + 80 * ASTR * 2;          // m-hi [128][88]
    uint32_t sBl = sBh + 128 * ASTR * 2;        // m-lo [128][88]

    int d0 = blockIdx.x * 128;
    int b  = blockIdx.y;
    int tid = threadIdx.x, wid = tid >> 5, lid = tid & 31;

    for (int i = tid; i < AGG_SMEM / 4; i += 128)
        asm volatile("st.shared.b32 [%0], %1;" :: "r"(sA + i * 4), "r"(0) : "memory");
    __syncthreads();

    const int* eb = edge + (size_t)b * SEQ * SEQ;
    for (int i = tid; i < SEQ * SEQ; i += 128) {
        int r = i / SEQ, c = i % SEQ;
        unsigned short v = (eb[i] != 0) ? (unsigned short)0x3F80 : (unsigned short)0;
        asm volatile("st.shared.u16 [%0], %1;"
                     :: "r"(sA + (c * ASTR + r) * 2), "h"(v) : "memory");
    }

    const __nv_bfloat16* Mh = mhi + (size_t)b * SEQ * DIM + d0;
    const __nv_bfloat16* Ml = mlo + (size_t)b * SEQ * DIM + d0;
    for (int i = tid; i < SEQ * 64; i += 128) {
        int r = i / 64, dd2 = i % 64;
        uint32_t vh = *(const uint32_t*)(Mh + (size_t)r * DIM + dd2 * 2);
        uint32_t vl = *(const uint32_t*)(Ml + (size_t)r * DIM + dd2 * 2);
        uint32_t o0 = ((dd2 * 2) * ASTR + r) * 2;
        uint32_t o1 = ((dd2 * 2 + 1) * ASTR + r) * 2;
        asm volatile("st.shared.u16 [%0], %1;" :: "r"(sBh + o0), "h"((unsigned short)(vh & 0xffff)) : "memory");
        asm volatile("st.shared.u16 [%0], %1;" :: "r"(sBh + o1), "h"((unsigned short)(vh >> 16)) : "memory");
        asm volatile("st.shared.u16 [%0], %1;" :: "r"(sBl + o0), "h"((unsigned short)(vl & 0xffff)) : "memory");
        asm volatile("st.shared.u16 [%0], %1;" :: "r"(sBl + o1), "h"((unsigned short)(vl >> 16)) : "memory");
    }
    __syncthreads();

    int t8 = lid >> 3, l8 = lid & 7;
    float acc[5][4][4];
    #pragma unroll
    for (int mt = 0; mt < 5; ++mt)
        #pragma unroll
        for (int an = 0; an < 4; ++an)
            #pragma unroll
            for (int r = 0; r < 4; ++r) acc[mt][an][r] = 0.f;

    #pragma unroll
    for (int k = 0; k < 5; ++k) {
        uint32_t bh2[2][4], bl2[2][4], a[5][4];
        #pragma unroll
        for (int g = 0; g < 2; ++g) {
            uint32_t rb = (uint32_t)((wid * 32 + g * 16 + (t8 >> 1) * 8 + l8) * (ASTR * 2)
                                     + ((t8 & 1) + k * 2) * 16);
            ldsm4(sBh + rb, bh2[g][0], bh2[g][1], bh2[g][2], bh2[g][3]);
            ldsm4(sBl + rb, bl2[g][0], bl2[g][1], bl2[g][2], bl2[g][3]);
        }
        #pragma unroll
        for (int mt = 0; mt < 5; ++mt) {
            uint32_t ra = sA + (uint32_t)((mt * 16 + (t8 & 1) * 8 + l8) * (ASTR * 2)
                                          + ((t8 >> 1) + k * 2) * 16);
            ldsm4(ra, a[mt][0], a[mt][1], a[mt][2], a[mt][3]);
        }
        #pragma unroll
        for (int mt = 0; mt < 5; ++mt)
            #pragma unroll
            for (int an = 0; an < 4; ++an) {
                uint32_t* bp = bh2[an >> 1];
                mma_bf16(acc[mt][an][0], acc[mt][an][1], acc[mt][an][2], acc[mt][an][3],
                         a[mt][0], a[mt][1], a[mt][2], a[mt][3],
                         bp[(an & 1) * 2], bp[(an & 1) * 2 + 1]);
            }
        #pragma unroll
        for (int mt = 0; mt < 5; ++mt)
            #pragma unroll
            for (int an = 0; an < 4; ++an) {
                uint32_t* bp = bl2[an >> 1];
                mma_bf16(acc[mt][an][0], acc[mt][an][1], acc[mt][an][2], acc[mt][an][3],
                         a[mt][0], a[mt][1], a[mt][2], a[mt][3],
                         bp[(an & 1) * 2], bp[(an & 1) * 2 + 1]);
            }
    }

    int er = lid >> 2, ec = (lid & 3) * 2;
    float2 bv[4];
    #pragma unroll
    for (int an = 0; an < 4; ++an)
        bv[an] = *(const float2*)(bias + d0 + wid * 32 + an * 8 + ec);

    #pragma unroll
    for (int mt = 0; mt < 5; ++mt) {
        #pragma unroll
        for (int h = 0; h < 2; ++h) {
            int c = mt * 16 + er + h * 8;
            if (c < SEQ) {
                #pragma unroll
                for (int an = 0; an < 4; ++an) {
                    int d = d0 + wid * 32 + an * 8 + ec;
                    float2 o;
                    o.x = acc[mt][an][h * 2 + 0] + bv[an].x;
                    o.y = acc[mt][an][h * 2 + 1] + bv[an].y;
                    *(float2*)(outF + ((size_t)b * SEQ + c) * DIM + d) = o;
                }
            }
        }
    }
}

// ===========================================================================
// out = logmap0(expmap0(leaky_relu(logmap0(expmap0(agg)))))
// ===========================================================================
__global__ void final_kernel(const float* __restrict__ in, float* __restrict__ out) {
    size_t base = (size_t)blockIdx.x * DIM;
    float4 v = ((const float4*)(in + base))[threadIdx.x];
    float ss = v.x * v.x + v.y * v.y + v.z * v.z + v.w * v.w;
    float sum = block_reduce_sum_256(ss);
    float n1 = fmaxf(sqrtf(sum), EPSF);
    float sc1 = atanhf(fminf(tanhf(n1), MAXNORM)) / n1;

    float u0 = sc1 * v.x; u0 = (u0 > 0.f) ? u0 : 0.01f * u0;
    float u1 = sc1 * v.y; u1 = (u1 > 0.f) ? u1 : 0.01f * u1;
    float u2 = sc1 * v.z; u2 = (u2 > 0.f) ? u2 : 0.01f * u2;
    float u3 = sc1 * v.w; u3 = (u3 > 0.f) ? u3 : 0.01f * u3;

    float ss2 = u0 * u0 + u1 * u1 + u2 * u2 + u3 * u3;
    float sum2 = block_reduce_sum_256(ss2);
    float n2 = fmaxf(sqrtf(sum2), EPSF);
    float sc2 = atanhf(fminf(tanhf(n2), MAXNORM)) / n2;

    float4 o;
    o.x = sc2 * u0; o.y = sc2 * u1; o.z = sc2 * u2; o.w = sc2 * u3;
    ((float4*)(out + base))[threadIdx.x] = o;
}

// ===========================================================================
extern "C" void kernel_launch(void* const* d_in, const int* in_sizes, int n_in,
                              void* d_out, int out_size) {
    const void*  tokens = d_in[0];
    const int*   edge   = (const int*)d_in[1];
    const float* tok_w  = (const float*)d_in[2];
    const float* pos_w  = (const float*)d_in[3];
    const float* mlp_w  = (const float*)d_in[4];
    const float* mlp_b  = (const float*)d_in[5];
    const float* gcn_w  = (const float*)d_in[6];
    const float* gcn_b  = (const float*)d_in[7];
    float* out = (float*)d_out;

    __nv_bfloat16 *ahi, *alo, *bhi, *blo, *whi, *wlo;
    float *bufF, *ssp;
    cudaGetSymbolAddress((void**)&ahi, g_ahi);
    cudaGetSymbolAddress((void**)&alo, g_alo);
    cudaGetSymbolAddress((void**)&bhi, g_bhi);
    cudaGetSymbolAddress((void**)&blo, g_blo);
    cudaGetSymbolAddress((void**)&whi, g_whi);
    cudaGetSymbolAddress((void**)&wlo, g_wlo);
    cudaGetSymbolAddress((void**)&bufF, g_bufF);
    cudaGetSymbolAddress((void**)&ssp, g_ss);

    cudaFuncSetAttribute(mega_gemm_kernel,
                         cudaFuncAttributeMaxDynamicSharedMemorySize, DSM_BYTES);
    cudaFuncSetAttribute(agg_mma_kernel,
                         cudaFuncAttributeMaxDynamicSharedMemorySize, AGG_SMEM);

    detect_tok_kernel<<<1, 256>>>((const unsigned long long*)tokens, NROWS / 2);
    embed_kernel<<<NROWS, 256>>>(tokens, tok_w, pos_w, ahi, alo, ssp);
    wsplit_kernel<<<dim3(32, 32, 6), dim3(32, 8)>>>(mlp_w, gcn_w, whi, wlo);

    // All 6 GEMMs in one persistent launch (mbarrier-pipelined, warp-decoupled)
    mega_gemm_kernel<<<NCTA, 256, DSM_BYTES>>>(ahi, alo, bhi, blo, whi, wlo,
                                               mlp_b, ssp);

    agg_mma_kernel<<<dim3(DIM / 128, BATCH), 128, AGG_SMEM>>>(ahi, alo, edge,
                                                              gcn_b + 3 * DIM, bufF);

    final_kernel<<<NROWS, 256>>>(bufF, out);
}

// round 14
// speedup vs baseline: 1.1424x; 1.1424x over previous
#include <cuda_runtime.h>
#include <cuda_bf16.h>
#include <math.h>
#include <stdint.h>

#define NROWS 19712   // 256*77
#define SEQ 77
#define BATCH 256
#define DIM 1024
#define EPSF 1e-15f
#define MAXNORM (1.0f - 1e-5f)

#define NCTA 296
#define NTILES_L 1232       // 154 m-tiles x 8 n-tiles per layer
#define NLAYER 6
#define TOT_TILES (NLAYER * NTILES_L)
#define NMT 154

// scratch (no allocations allowed)
__device__ __nv_bfloat16 g_ahi[(size_t)NROWS * DIM];
__device__ __nv_bfloat16 g_alo[(size_t)NROWS * DIM];
__device__ __nv_bfloat16 g_bhi[(size_t)NROWS * DIM];
__device__ __nv_bfloat16 g_blo[(size_t)NROWS * DIM];
__device__ float g_bufF[(size_t)NROWS * DIM];
__device__ __nv_bfloat16 g_whi[(size_t)6 * DIM * DIM];  // transposed [N][K]
__device__ __nv_bfloat16 g_wlo[(size_t)6 * DIM * DIM];
__device__ float g_ss[NROWS];              // per-row sum of squares (fused he)
__device__ unsigned g_cnt[NLAYER * NMT];   // per-(layer, m-block) completion
__device__ int g_tok64;

// ===========================================================================
// PTX helpers (baseline sm_80+ features only — valid at compute_103)
// ===========================================================================
__device__ __forceinline__ uint32_t smem_u32(const void* p) {
    uint32_t a;
    asm("{ .reg .u64 t; cvta.to.shared.u64 t, %1; cvt.u32.u64 %0, t; }" : "=r"(a) : "l"(p));
    return a;
}
__device__ __forceinline__ void cp_async16(uint32_t dst, const void* src) {
    asm volatile("cp.async.cg.shared.global [%0], [%1], 16;" :: "r"(dst), "l"(src) : "memory");
}
__device__ __forceinline__ void cp_commit() {
    asm volatile("cp.async.commit_group;" ::: "memory");
}
#define CP_WAIT(n) asm volatile("cp.async.wait_group %0;" :: "n"(n) : "memory")

__device__ __forceinline__ void ldsm4(uint32_t addr, uint32_t& r0, uint32_t& r1,
                                      uint32_t& r2, uint32_t& r3) {
    asm volatile("ldmatrix.sync.aligned.m8n8.x4.shared.b16 {%0,%1,%2,%3}, [%4];"
                 : "=r"(r0), "=r"(r1), "=r"(r2), "=r"(r3) : "r"(addr));
}
__device__ __forceinline__ void mma_bf16(float& d0, float& d1, float& d2, float& d3,
                                         uint32_t a0, uint32_t a1, uint32_t a2, uint32_t a3,
                                         uint32_t b0, uint32_t b1) {
    asm volatile("mma.sync.aligned.m16n8k16.row.col.f32.bf16.bf16.f32 "
                 "{%0,%1,%2,%3},{%4,%5,%6,%7},{%8,%9},{%0,%1,%2,%3};"
                 : "+f"(d0), "+f"(d1), "+f"(d2), "+f"(d3)
                 : "r"(a0), "r"(a1), "r"(a2), "r"(a3), "r"(b0), "r"(b1));
}
__device__ __forceinline__ void split_bf16(float v, __nv_bfloat16& hi, __nv_bfloat16& lo) {
    hi = __float2bfloat16(v);
    lo = __float2bfloat16(v - __bfloat162float(hi));
}

// ===========================================================================
// Token layout detection + counter zeroing
// ===========================================================================
__global__ void detect_tok_kernel(const unsigned long long* __restrict__ w, int nwords) {
    __shared__ int flag;
    if (threadIdx.x == 0) flag = 0;
    __syncthreads();
    int bad = 0;
    for (int i = threadIdx.x; i < nwords; i += blockDim.x)
        if (w[i] >> 32) { bad = 1; break; }
    if (bad) flag = 1;
    __syncthreads();
    if (threadIdx.x == 0) g_tok64 = flag ? 0 : 1;
    for (int i = threadIdx.x; i < NLAYER * NMT; i += blockDim.x) g_cnt[i] = 0;
}

// ===========================================================================
// Embedding -> hi/lo bf16 split (also zeroes g_ss for this row)
// ===========================================================================
__global__ void embed_kernel(const void* __restrict__ tokens,
                             const float* __restrict__ tok_w,
                             const float* __restrict__ pos_w,
                             __nv_bfloat16* __restrict__ xhi,
                             __nv_bfloat16* __restrict__ xlo,
                             float* __restrict__ ss) {
    int row = blockIdx.x;
    int s = row % SEQ;
    if (threadIdx.x == 0) ss[row] = 0.f;
    long long t;
    if (g_tok64) t = ((const long long*)tokens)[row];
    else         t = (long long)(((const int*)tokens)[row]);
    int i = threadIdx.x;
    float4 a = ((const float4*)(tok_w + (size_t)t * DIM))[i];
    float4 p = ((const float4*)(pos_w + (size_t)s * DIM))[i];
    float v[4] = {a.x + p.x, a.y + p.y, a.z + p.z, a.w + p.w};
    __nv_bfloat16 h[4], l[4];
    #pragma unroll
    for (int q = 0; q < 4; ++q) split_bf16(v[q], h[q], l[q]);
    size_t base = (size_t)row * DIM + i * 4;
    *(uint2*)(xhi + base) = *(uint2*)h;
    *(uint2*)(xlo + base) = *(uint2*)l;
}

// ===========================================================================
// Weight transpose + split
// ===========================================================================
__global__ void wsplit_kernel(const float* __restrict__ mlp_w,
                              const float* __restrict__ gcn_w,
                              __nv_bfloat16* __restrict__ whi,
                              __nv_bfloat16* __restrict__ wlo) {
    __shared__ float t[32][33];
    int mat = blockIdx.z;
    const float* src = (mat < 5) ? mlp_w + (size_t)mat * DIM * DIM
                                 : gcn_w + (size_t)3 * DIM * DIM;
    size_t doff = (size_t)mat * DIM * DIM;
    int n0 = blockIdx.x * 32, k0 = blockIdx.y * 32;
    for (int i = threadIdx.y; i < 32; i += 8)
        t[i][threadIdx.x] = src[(size_t)(k0 + i) * DIM + n0 + threadIdx.x];
    __syncthreads();
    for (int i = threadIdx.y; i < 32; i += 8) {
        float v = t[threadIdx.x][i];
        __nv_bfloat16 h, l;
        split_bf16(v, h, l);
        size_t d = doff + (size_t)(n0 + i) * DIM + k0 + threadIdx.x;
        whi[d] = h; wlo[d] = l;
    }
}

// ===========================================================================
// Persistent fused 6-layer GEMM chain (R12 structure: CP_WAIT+syncthreads).
// Race fix vs R12: one __syncthreads() at tile start so no warp overwrites
// a stage another warp is still reading from the previous tile.
// Inner chunk: interleaved ldsm/MMA (pass-1 operands first).
// ===========================================================================
#define STAGES 3
#define NCHUNK 32
#define TILE_BYTES 8192               // 128 rows x 64B
#define STAGE_BYTES (4 * TILE_BYTES)  // 32 KB
#define DSM_BYTES (STAGES * STAGE_BYTES)  // 96 KB

__global__ __launch_bounds__(256, 2) void mega_gemm_kernel(
    __nv_bfloat16* __restrict__ ahi, __nv_bfloat16* __restrict__ alo,
    __nv_bfloat16* __restrict__ bhi, __nv_bfloat16* __restrict__ blo,
    const __nv_bfloat16* __restrict__ whi, const __nv_bfloat16* __restrict__ wlo,
    const float* __restrict__ mlp_b, float* __restrict__ ssp)
{
    extern __shared__ char dsm_raw[];
    uint32_t dsm = smem_u32(dsm_raw);

    int tid = threadIdx.x, wid = tid >> 5, lid = tid & 31;
    int wm = wid & 1, wn = wid >> 1;

    // ldmatrix lane addressing (loop-invariant)
    int t8 = lid >> 3, l8 = lid & 7;
    uint32_t sw = (uint32_t)((l8 >> 1) & 3);
    uint32_t a_row = (uint32_t)(wm * 64 + (t8 & 1) * 8 + l8);
    uint32_t b_row = (uint32_t)(wn * 32 + (t8 >> 1) * 8 + l8);
    uint32_t a_c = (uint32_t)(t8 >> 1);
    uint32_t b_c = (uint32_t)(t8 & 1);
    int er = lid >> 2, ec = (lid & 3) * 2;

    for (int t = blockIdx.x; t < TOT_TILES; t += NCTA) {
        int L  = t / NTILES_L;
        int r  = t - L * NTILES_L;
        int mt = r >> 3, nt = r & 7;
        int bm = mt << 7, bn = nt << 7;

        const __nv_bfloat16* Ahi = (L & 1) ? bhi : ahi;
        const __nv_bfloat16* Alo = (L & 1) ? blo : alo;
        __nv_bfloat16* Ohi = (L & 1) ? ahi : bhi;
        __nv_bfloat16* Olo = (L & 1) ? alo : blo;
        const __nv_bfloat16* Bhi = whi + (size_t)L * DIM * DIM;
        const __nv_bfloat16* Blo = wlo + (size_t)L * DIM * DIM;
        const float* bias = (L < 5) ? mlp_b + L * DIM : nullptr;
        int applySilu = (L < 4);
        float* ssAcc = (L == 4) ? ssp : nullptr;
        const float* ssScale = (L == 5) ? ssp : nullptr;

        // ---- dependency wait + stage-reuse safety barrier ----
        if (L > 0 && tid == 0) {
            volatile unsigned* f = &g_cnt[(L - 1) * NMT + mt];
            while (*f < 8u) __nanosleep(64);
        }
        __syncthreads();   // also guarantees prior tile's smem reads are done

        float acc[4][4][4];
        #pragma unroll
        for (int i = 0; i < 4; ++i)
            #pragma unroll
            for (int j = 0; j < 4; ++j)
                #pragma unroll
                for (int q = 0; q < 4; ++q) acc[i][j][q] = 0.f;

        auto issue = [&](int j) {
            int k0 = j * 32;
            uint32_t st = dsm + (j % STAGES) * STAGE_BYTES;
            #pragma unroll
            for (int u = 0; u < 8; ++u) {
                int i = tid + u * 256;
                int tt = i >> 9, rr = (i >> 2) & 127, cc = i & 3;
                const __nv_bfloat16* gb;
                if (tt == 0)      gb = Ahi + (size_t)(bm + rr) * DIM;
                else if (tt == 1) gb = Alo + (size_t)(bm + rr) * DIM;
                else if (tt == 2) gb = Bhi + (size_t)(bn + rr) * DIM;
                else              gb = Blo + (size_t)(bn + rr) * DIM;
                uint32_t daddr = st + tt * TILE_BYTES + rr * 64 + (((cc ^ ((rr >> 1) & 3))) * 16);
                cp_async16(daddr, gb + k0 + cc * 8);
            }
            cp_commit();
        };

        issue(0); issue(1);

        for (int j = 0; j < NCHUNK; ++j) {
            if (j == NCHUNK - 1) { CP_WAIT(0); } else { CP_WAIT(1); }
            __syncthreads();
            if (j + 2 < NCHUNK) issue(j + 2);

            uint32_t st = dsm + (j % STAGES) * STAGE_BYTES;
            #pragma unroll
            for (int ks = 0; ks < 2; ++ks) {
                uint32_t a_off = ((a_c + ks * 2) ^ sw) * 16;
                uint32_t b_off = ((b_c + ks * 2) ^ sw) * 16;
                uint32_t ah[4][4], al[4][4], bh2[2][4], bl2[2][4];
                // pass-1 operands first: MMAs can start after 6 ldsm
                #pragma unroll
                for (int np = 0; np < 2; ++np) {
                    uint32_t rb = st + 2 * TILE_BYTES + (b_row + np * 16) * 64 + b_off;
                    ldsm4(rb, bh2[np][0], bh2[np][1], bh2[np][2], bh2[np][3]);
                }
                #pragma unroll
                for (int am = 0; am < 4; ++am) {
                    uint32_t ra = st + (a_row + am * 16) * 64 + a_off;
                    ldsm4(ra, ah[am][0], ah[am][1], ah[am][2], ah[am][3]);
                }
                #pragma unroll
                for (int am = 0; am < 4; ++am)
                    #pragma unroll
                    for (int an = 0; an < 4; ++an) {
                        uint32_t* bp = bh2[an >> 1];
                        mma_bf16(acc[am][an][0], acc[am][an][1], acc[am][an][2], acc[am][an][3],
                                 ah[am][0], ah[am][1], ah[am][2], ah[am][3],
                                 bp[(an & 1) * 2], bp[(an & 1) * 2 + 1]);
                    }
                // pass-2 operands load under pass-1 MMAs
                #pragma unroll
                for (int am = 0; am < 4; ++am) {
                    uint32_t ra = st + TILE_BYTES + (a_row + am * 16) * 64 + a_off;
                    ldsm4(ra, al[am][0], al[am][1], al[am][2], al[am][3]);
                }
                #pragma unroll
                for (int am = 0; am < 4; ++am)
                    #pragma unroll
                    for (int an = 0; an < 4; ++an) {
                        uint32_t* bp = bh2[an >> 1];
                        mma_bf16(acc[am][an][0], acc[am][an][1], acc[am][an][2], acc[am][an][3],
                                 al[am][0], al[am][1], al[am][2], al[am][3],
                                 bp[(an & 1) * 2], bp[(an & 1) * 2 + 1]);
                    }
                // pass-3 operands load under pass-2 MMAs
                #pragma unroll
                for (int np = 0; np < 2; ++np) {
                    uint32_t rb = st + 3 * TILE_BYTES + (b_row + np * 16) * 64 + b_off;
                    ldsm4(rb, bl2[np][0], bl2[np][1], bl2[np][2], bl2[np][3]);
                }
                #pragma unroll
                for (int am = 0; am < 4; ++am)
                    #pragma unroll
                    for (int an = 0; an < 4; ++an) {
                        uint32_t* bp = bl2[an >> 1];
                        mma_bf16(acc[am][an][0], acc[am][an][1], acc[am][an][2], acc[am][an][3],
                                 ah[am][0], ah[am][1], ah[am][2], ah[am][3],
                                 bp[(an & 1) * 2], bp[(an & 1) * 2 + 1]);
                    }
            }
        }

        // ---- epilogue ----
        float2 bv[4];
        #pragma unroll
        for (int an = 0; an < 4; ++an)
            bv[an] = bias ? *(const float2*)(bias + bn + wn * 32 + an * 8 + ec)
                          : make_float2(0.f, 0.f);

        #pragma unroll
        for (int am = 0; am < 4; ++am) {
            #pragma unroll
            for (int h = 0; h < 2; ++h) {
                int row = bm + wm * 64 + am * 16 + er + h * 8;
                float sc = 1.f;
                if (ssScale) {
                    float ssv = __ldg(ssScale + row);
                    float n = fmaxf(sqrtf(ssv), EPSF);
                    sc = atanhf(fminf(tanhf(n), MAXNORM)) / n;
                }
                float sspv = 0.f;
                #pragma unroll
                for (int an = 0; an < 4; ++an) {
                    int col = bn + wn * 32 + an * 8 + ec;
                    float v0 = acc[am][an][h * 2 + 0] + bv[an].x;
                    float v1 = acc[am][an][h * 2 + 1] + bv[an].y;
                    if (applySilu) {
                        v0 = v0 / (1.0f + __expf(-v0));
                        v1 = v1 / (1.0f + __expf(-v1));
                    }
                    if (ssAcc) sspv += v0 * v0 + v1 * v1;
                    v0 *= sc; v1 *= sc;
                    __nv_bfloat16 h0, l0, h1, l1;
                    split_bf16(v0, h0, l0);
                    split_bf16(v1, h1, l1);
                    __nv_bfloat16 hp[2] = {h0, h1}, lp[2] = {l0, l1};
                    *(uint32_t*)(Ohi + (size_t)row * DIM + col) = *(uint32_t*)hp;
                    *(uint32_t*)(Olo + (size_t)row * DIM + col) = *(uint32_t*)lp;
                }
                if (ssAcc) {
                    sspv += __shfl_xor_sync(0xffffffffu, sspv, 1);
                    sspv += __shfl_xor_sync(0xffffffffu, sspv, 2);
                    if ((lid & 3) == 0) atomicAdd(ssAcc + row, sspv);
                }
            }
        }

        // ---- publish completion ----
        __threadfence();
        __syncthreads();
        if (tid == 0) atomicAdd(&g_cnt[L * NMT + mt], 1u);
    }
}

// ===========================================================================
// block reduction over 256 threads
// ===========================================================================
__device__ __forceinline__ float block_reduce_sum_256(float v) {
    __shared__ float s[8];
    __syncthreads();
    int lane = threadIdx.x & 31, w = threadIdx.x >> 5;
    #pragma unroll
    for (int o = 16; o; o >>= 1) v += __shfl_down_sync(0xffffffffu, v, o);
    if (lane == 0) s[w] = v;
    __syncthreads();
    if (threadIdx.x == 0) {
        float t = 0.f;
        #pragma unroll
        for (int i = 0; i < 8; ++i) t += s[i];
        s[0] = t;
    }
    __syncthreads();
    return s[0];
}

// ===========================================================================
// Tensor-core aggregation: agg[b,c,d] = sum_r adj[r,c]*m[r,d] + bias[d].
// ===========================================================================
#define ASTR 88                               // elements; 176B row stride
#define AGG_SMEM ((80 + 2 * 128) * ASTR * 2)  // 59136 B

__global__ __launch_bounds__(128) void agg_mma_kernel(
    const __nv_bfloat16* __restrict__ mhi, const __nv_bfloat16* __restrict__ mlo,
    const int* __restrict__ edge, const float* __restrict__ bias,
    float* __restrict__ outF)
{
    extern __shared__ char agg_raw[];
    uint32_t sA  = smem_u32(agg_raw);           // adjT [80][88]
    uint32_t sBh = sA + 80 * ASTR * 2;          // m-hi [128][88]
    uint32_t sBl = sBh + 128 * ASTR * 2;        // m-lo [128][88]

    int d0 = blockIdx.x * 128;
    int b  = blockIdx.y;
    int tid = threadIdx.x, wid = tid >> 5, lid = tid & 31;

    for (int i = tid; i < AGG_SMEM / 4; i += 128)
        asm volatile("st.shared.b32 [%0], %1;" :: "r"(sA + i * 4), "r"(0) : "memory");
    __syncthreads();

    const int* eb = edge + (size_t)b * SEQ * SEQ;
    for (int i = tid; i < SEQ * SEQ; i += 128) {
        int r = i / SEQ, c = i % SEQ;
        unsigned short v = (eb[i] != 0) ? (unsigned short)0x3F80 : (unsigned short)0;
        asm volatile("st.shared.u16 [%0], %1;"
                     :: "r"(sA + (c * ASTR + r) * 2), "h"(v) : "memory");
    }

    const __nv_bfloat16* Mh = mhi + (size_t)b * SEQ * DIM + d0;
    const __nv_bfloat16* Ml = mlo + (size_t)b * SEQ * DIM + d0;
    for (int i = tid; i < SEQ * 64; i += 128) {
        int r = i / 64, dd2 = i % 64;
        uint32_t vh = *(const uint32_t*)(Mh + (size_t)r * DIM + dd2 * 2);
        uint32_t vl = *(const uint32_t*)(Ml + (size_t)r * DIM + dd2 * 2);
        uint32_t o0 = ((dd2 * 2) * ASTR + r) * 2;
        uint32_t o1 = ((dd2 * 2 + 1) * ASTR + r) * 2;
        asm volatile("st.shared.u16 [%0], %1;" :: "r"(sBh + o0), "h"((unsigned short)(vh & 0xffff)) : "memory");
        asm volatile("st.shared.u16 [%0], %1;" :: "r"(sBh + o1), "h"((unsigned short)(vh >> 16)) : "memory");
        asm volatile("st.shared.u16 [%0], %1;" :: "r"(sBl + o0), "h"((unsigned short)(vl & 0xffff)) : "memory");
        asm volatile("st.shared.u16 [%0], %1;" :: "r"(sBl + o1), "h"((unsigned short)(vl >> 16)) : "memory");
    }
    __syncthreads();

    int t8 = lid >> 3, l8 = lid & 7;
    float acc[5][4][4];
    #pragma unroll
    for (int mt = 0; mt < 5; ++mt)
        #pragma unroll
        for (int an = 0; an < 4; ++an)
            #pragma unroll
            for (int r = 0; r < 4; ++r) acc[mt][an][r] = 0.f;

    #pragma unroll
    for (int k = 0; k < 5; ++k) {
        uint32_t bh2[2][4], bl2[2][4], a[5][4];
        #pragma unroll
        for (int g = 0; g < 2; ++g) {
            uint32_t rb = (uint32_t)((wid * 32 + g * 16 + (t8 >> 1) * 8 + l8) * (ASTR * 2)
                                     + ((t8 & 1) + k * 2) * 16);
            ldsm4(sBh + rb, bh2[g][0], bh2[g][1], bh2[g][2], bh2[g][3]);
            ldsm4(sBl + rb, bl2[g][0], bl2[g][1], bl2[g][2], bl2[g][3]);
        }
        #pragma unroll
        for (int mt = 0; mt < 5; ++mt) {
            uint32_t ra = sA + (uint32_t)((mt * 16 + (t8 & 1) * 8 + l8) * (ASTR * 2)
                                          + ((t8 >> 1) + k * 2) * 16);
            ldsm4(ra, a[mt][0], a[mt][1], a[mt][2], a[mt][3]);
        }
        #pragma unroll
        for (int mt = 0; mt < 5; ++mt)
            #pragma unroll
            for (int an = 0; an < 4; ++an) {
                uint32_t* bp = bh2[an >> 1];
                mma_bf16(acc[mt][an][0], acc[mt][an][1], acc[mt][an][2], acc[mt][an][3],
                         a[mt][0], a[mt][1], a[mt][2], a[mt][3],
                         bp[(an & 1) * 2], bp[(an & 1) * 2 + 1]);
            }
        #pragma unroll
        for (int mt = 0; mt < 5; ++mt)
            #pragma unroll
            for (int an = 0; an < 4; ++an) {
                uint32_t* bp = bl2[an >> 1];
                mma_bf16(acc[mt][an][0], acc[mt][an][1], acc[mt][an][2], acc[mt][an][3],
                         a[mt][0], a[mt][1], a[mt][2], a[mt][3],
                         bp[(an & 1) * 2], bp[(an & 1) * 2 + 1]);
            }
    }

    int er = lid >> 2, ec = (lid & 3) * 2;
    float2 bv[4];
    #pragma unroll
    for (int an = 0; an < 4; ++an)
        bv[an] = *(const float2*)(bias + d0 + wid * 32 + an * 8 + ec);

    #pragma unroll
    for (int mt = 0; mt < 5; ++mt) {
        #pragma unroll
        for (int h = 0; h < 2; ++h) {
            int c = mt * 16 + er + h * 8;
            if (c < SEQ) {
                #pragma unroll
                for (int an = 0; an < 4; ++an) {
                    int d = d0 + wid * 32 + an * 8 + ec;
                    float2 o;
                    o.x = acc[mt][an][h * 2 + 0] + bv[an].x;
                    o.y = acc[mt][an][h * 2 + 1] + bv[an].y;
                    *(float2*)(outF + ((size_t)b * SEQ + c) * DIM + d) = o;
                }
            }
        }
    }
}

// ===========================================================================
// out = logmap0(expmap0(leaky_relu(logmap0(expmap0(agg)))))
// ===========================================================================
__global__ void final_kernel(const float* __restrict__ in, float* __restrict__ out) {
    size_t base = (size_t)blockIdx.x * DIM;
    float4 v = ((const float4*)(in + base))[threadIdx.x];
    float ss = v.x * v.x + v.y * v.y + v.z * v.z + v.w * v.w;
    float sum = block_reduce_sum_256(ss);
    float n1 = fmaxf(sqrtf(sum), EPSF);
    float sc1 = atanhf(fminf(tanhf(n1), MAXNORM)) / n1;

    float u0 = sc1 * v.x; u0 = (u0 > 0.f) ? u0 : 0.01f * u0;
    float u1 = sc1 * v.y; u1 = (u1 > 0.f) ? u1 : 0.01f * u1;
    float u2 = sc1 * v.z; u2 = (u2 > 0.f) ? u2 : 0.01f * u2;
    float u3 = sc1 * v.w; u3 = (u3 > 0.f) ? u3 : 0.01f * u3;

    float ss2 = u0 * u0 + u1 * u1 + u2 * u2 + u3 * u3;
    float sum2 = block_reduce_sum_256(ss2);
    float n2 = fmaxf(sqrtf(sum2), EPSF);
    float sc2 = atanhf(fminf(tanhf(n2), MAXNORM)) / n2;

    float4 o;
    o.x = sc2 * u0; o.y = sc2 * u1; o.z = sc2 * u2; o.w = sc2 * u3;
    ((float4*)(out + base))[threadIdx.x] = o;
}

// ===========================================================================
extern "C" void kernel_launch(void* const* d_in, const int* in_sizes, int n_in,
                              void* d_out, int out_size) {
    const void*  tokens = d_in[0];
    const int*   edge   = (const int*)d_in[1];
    const float* tok_w  = (const float*)d_in[2];
    const float* pos_w  = (const float*)d_in[3];
    const float* mlp_w  = (const float*)d_in[4];
    const float* mlp_b  = (const float*)d_in[5];
    const float* gcn_w  = (const float*)d_in[6];
    const float* gcn_b  = (const float*)d_in[7];
    float* out = (float*)d_out;

    __nv_bfloat16 *ahi, *alo, *bhi, *blo, *whi, *wlo;
    float *bufF, *ssp;
    cudaGetSymbolAddress((void**)&ahi, g_ahi);
    cudaGetSymbolAddress((void**)&alo, g_alo);
    cudaGetSymbolAddress((void**)&bhi, g_bhi);
    cudaGetSymbolAddress((void**)&blo, g_blo);
    cudaGetSymbolAddress((void**)&whi, g_whi);
    cudaGetSymbolAddress((void**)&wlo, g_wlo);
    cudaGetSymbolAddress((void**)&bufF, g_bufF);
    cudaGetSymbolAddress((void**)&ssp, g_ss);

    cudaFuncSetAttribute(mega_gemm_kernel,
                         cudaFuncAttributeMaxDynamicSharedMemorySize, DSM_BYTES);
    cudaFuncSetAttribute(agg_mma_kernel,
                         cudaFuncAttributeMaxDynamicSharedMemorySize, AGG_SMEM);

    detect_tok_kernel<<<1, 256>>>((const unsigned long long*)tokens, NROWS / 2);
    embed_kernel<<<NROWS, 256>>>(tokens, tok_w, pos_w, ahi, alo, ssp);
    wsplit_kernel<<<dim3(32, 32, 6), dim3(32, 8)>>>(mlp_w, gcn_w, whi, wlo);

    // All 6 GEMMs in one persistent launch (R12 structure + race fix)
    mega_gemm_kernel<<<NCTA, 256, DSM_BYTES>>>(ahi, alo, bhi, blo, whi, wlo,
                                               mlp_b, ssp);

    agg_mma_kernel<<<dim3(DIM / 128, BATCH), 128, AGG_SMEM>>>(ahi, alo, edge,
                                                              gcn_b + 3 * DIM, bufF);

    final_kernel<<<NROWS, 256>>>(bufF, out);
}

// round 15
// speedup vs baseline: 1.1518x; 1.0082x over previous
#include <cuda_runtime.h>
#include <cuda_bf16.h>
#include <math.h>
#include <stdint.h>

#define NROWS 19712   // 256*77
#define SEQ 77
#define BATCH 256
#define DIM 1024
#define EPSF 1e-15f
#define MAXNORM (1.0f - 1e-5f)

#define NCTA 296
#define NTILES_L 1232       // 154 m-tiles x 8 n-tiles per layer
#define NLAYER 6
#define TOT_TILES (NLAYER * NTILES_L)
#define NMT 154
#define NWCTA 142           // CTAs 154..295 do weight split

// scratch (no allocations allowed)
__device__ __nv_bfloat16 g_ahi[(size_t)NROWS * DIM];
__device__ __nv_bfloat16 g_alo[(size_t)NROWS * DIM];
__device__ __nv_bfloat16 g_bhi[(size_t)NROWS * DIM];
__device__ __nv_bfloat16 g_blo[(size_t)NROWS * DIM];
__device__ float g_bufF[(size_t)NROWS * DIM];
__device__ __nv_bfloat16 g_whi[(size_t)6 * DIM * DIM];  // transposed [N][K]
__device__ __nv_bfloat16 g_wlo[(size_t)6 * DIM * DIM];
__device__ float g_ss[NROWS];              // per-row sum of squares (fused he)
__device__ unsigned g_cnt[NLAYER * NMT];   // per-(layer, m-block) completion
__device__ unsigned g_emb[NMT];            // embed-tile ready flags
__device__ unsigned g_wcnt[NLAYER];        // weight-split completion (== NWCTA)
__device__ int g_tok64;

// ===========================================================================
// PTX helpers (baseline sm_80+ features only — valid at compute_103)
// ===========================================================================
__device__ __forceinline__ uint32_t smem_u32(const void* p) {
    uint32_t a;
    asm("{ .reg .u64 t; cvta.to.shared.u64 t, %1; cvt.u32.u64 %0, t; }" : "=r"(a) : "l"(p));
    return a;
}
__device__ __forceinline__ void cp_async16(uint32_t dst, const void* src) {
    asm volatile("cp.async.cg.shared.global [%0], [%1], 16;" :: "r"(dst), "l"(src) : "memory");
}
__device__ __forceinline__ void cp_commit() {
    asm volatile("cp.async.commit_group;" ::: "memory");
}
#define CP_WAIT(n) asm volatile("cp.async.wait_group %0;" :: "n"(n) : "memory")

__device__ __forceinline__ void ldsm4(uint32_t addr, uint32_t& r0, uint32_t& r1,
                                      uint32_t& r2, uint32_t& r3) {
    asm volatile("ldmatrix.sync.aligned.m8n8.x4.shared.b16 {%0,%1,%2,%3}, [%4];"
                 : "=r"(r0), "=r"(r1), "=r"(r2), "=r"(r3) : "r"(addr));
}
__device__ __forceinline__ void mma_bf16(float& d0, float& d1, float& d2, float& d3,
                                         uint32_t a0, uint32_t a1, uint32_t a2, uint32_t a3,
                                         uint32_t b0, uint32_t b1) {
    asm volatile("mma.sync.aligned.m16n8k16.row.col.f32.bf16.bf16.f32 "
                 "{%0,%1,%2,%3},{%4,%5,%6,%7},{%8,%9},{%0,%1,%2,%3};"
                 : "+f"(d0), "+f"(d1), "+f"(d2), "+f"(d3)
                 : "r"(a0), "r"(a1), "r"(a2), "r"(a3), "r"(b0), "r"(b1));
}
__device__ __forceinline__ void split_bf16(float v, __nv_bfloat16& hi, __nv_bfloat16& lo) {
    hi = __float2bfloat16(v);
    lo = __float2bfloat16(v - __bfloat162float(hi));
}

// ===========================================================================
// Token layout detection + flag zeroing
// ===========================================================================
__global__ void detect_tok_kernel(const unsigned long long* __restrict__ w, int nwords) {
    __shared__ int flag;
    if (threadIdx.x == 0) flag = 0;
    __syncthreads();
    int bad = 0;
    for (int i = threadIdx.x; i < nwords; i += blockDim.x)
        if (w[i] >> 32) { bad = 1; break; }
    if (bad) flag = 1;
    __syncthreads();
    if (threadIdx.x == 0) g_tok64 = flag ? 0 : 1;
    for (int i = threadIdx.x; i < NLAYER * NMT; i += blockDim.x) g_cnt[i] = 0;
    for (int i = threadIdx.x; i < NMT; i += blockDim.x) g_emb[i] = 0;
    if (threadIdx.x < NLAYER) g_wcnt[threadIdx.x] = 0;
}

// ===========================================================================
// Persistent fused kernel:
//   Phase 0: CTAs 0..153 embed one 128-row m-tile (token+pos -> hi/lo split);
//            CTAs 154..295 transpose+split the 6 weight matrices.
//            Completion published via g_emb / g_wcnt.
//   Phase 1: 6-layer GEMM chain (R14 hot loop, untouched), tile deps now also
//            gate on g_emb (L0) and g_wcnt[L].
// ===========================================================================
#define STAGES 3
#define NCHUNK 32
#define TILE_BYTES 8192               // 128 rows x 64B
#define STAGE_BYTES (4 * TILE_BYTES)  // 32 KB
#define DSM_BYTES (STAGES * STAGE_BYTES)  // 96 KB

__global__ __launch_bounds__(256, 2) void mega_gemm_kernel(
    const void* __restrict__ tokens,
    const float* __restrict__ tok_w, const float* __restrict__ pos_w,
    const float* __restrict__ mlp_w, const float* __restrict__ gcn_w,
    __nv_bfloat16* __restrict__ ahi, __nv_bfloat16* __restrict__ alo,
    __nv_bfloat16* __restrict__ bhi, __nv_bfloat16* __restrict__ blo,
    __nv_bfloat16* __restrict__ whi, __nv_bfloat16* __restrict__ wlo,
    const float* __restrict__ mlp_b, float* __restrict__ ssp)
{
    extern __shared__ char dsm_raw[];
    uint32_t dsm = smem_u32(dsm_raw);

    int tid = threadIdx.x, wid = tid >> 5, lid = tid & 31;
    int cta = blockIdx.x;
    int wm = wid & 1, wn = wid >> 1;

    // ---------------- Phase 0 ----------------
    if (cta < NMT) {
        // embed m-tile `cta`: rows [cta*128, cta*128+128)
        int row0 = cta * 128;
        if (tid < 128) ssp[row0 + tid] = 0.f;
        int tok64 = g_tok64;
        for (int u = 0; u < 128; ++u) {
            int row = row0 + u;
            long long t;
            if (tok64) t = ((const long long*)tokens)[row];
            else       t = (long long)(((const int*)tokens)[row]);
            int s = row % SEQ;
            float4 a = ((const float4*)(tok_w + (size_t)t * DIM))[tid];
            float4 p = ((const float4*)(pos_w + (size_t)s * DIM))[tid];
            float v[4] = {a.x + p.x, a.y + p.y, a.z + p.z, a.w + p.w};
            __nv_bfloat16 h[4], l[4];
            #pragma unroll
            for (int q = 0; q < 4; ++q) split_bf16(v[q], h[q], l[q]);
            size_t base = (size_t)row * DIM + tid * 4;
            *(uint2*)(ahi + base) = *(uint2*)h;
            *(uint2*)(alo + base) = *(uint2*)l;
        }
        __threadfence();
        __syncthreads();
        if (tid == 0) atomicExch(&g_emb[cta], 1u);
    } else {
        // weight transpose+split, matrices in order 0..5 (W0 first)
        int wcta = cta - NMT;   // 0..141
        float* tsm = (float*)dsm_raw;   // 32x33 tile
        int x = tid & 31, y = tid >> 5; // y in 0..7
        for (int mat = 0; mat < NLAYER; ++mat) {
            const float* src = (mat < 5) ? mlp_w + (size_t)mat * DIM * DIM
                                         : gcn_w + (size_t)3 * DIM * DIM;
            size_t doff = (size_t)mat * DIM * DIM;
            for (int tidx = wcta; tidx < 1024; tidx += NWCTA) {
                int n0 = (tidx & 31) * 32, k0 = (tidx >> 5) * 32;
                #pragma unroll
                for (int i = y; i < 32; i += 8)
                    tsm[i * 33 + x] = src[(size_t)(k0 + i) * DIM + n0 + x];
                __syncthreads();
                #pragma unroll
                for (int i = y; i < 32; i += 8) {
                    float v = tsm[x * 33 + i];
                    __nv_bfloat16 h, l;
                    split_bf16(v, h, l);
                    size_t d = doff + (size_t)(n0 + i) * DIM + k0 + x;
                    whi[d] = h; wlo[d] = l;
                }
                __syncthreads();
            }
            __threadfence();
            __syncthreads();
            if (tid == 0) atomicAdd(&g_wcnt[mat], 1u);
        }
    }

    // ---------------- Phase 1: GEMM tile loop (R14 hot loop) ----------------
    int t8 = lid >> 3, l8 = lid & 7;
    uint32_t sw = (uint32_t)((l8 >> 1) & 3);
    uint32_t a_row = (uint32_t)(wm * 64 + (t8 & 1) * 8 + l8);
    uint32_t b_row = (uint32_t)(wn * 32 + (t8 >> 1) * 8 + l8);
    uint32_t a_c = (uint32_t)(t8 >> 1);
    uint32_t b_c = (uint32_t)(t8 & 1);
    int er = lid >> 2, ec = (lid & 3) * 2;

    for (int t = cta; t < TOT_TILES; t += NCTA) {
        int L  = t / NTILES_L;
        int r  = t - L * NTILES_L;
        int mt = r >> 3, nt = r & 7;
        int bm = mt << 7, bn = nt << 7;

        const __nv_bfloat16* Ahi = (L & 1) ? bhi : ahi;
        const __nv_bfloat16* Alo = (L & 1) ? blo : alo;
        __nv_bfloat16* Ohi = (L & 1) ? ahi : bhi;
        __nv_bfloat16* Olo = (L & 1) ? alo : blo;
        const __nv_bfloat16* Bhi = whi + (size_t)L * DIM * DIM;
        const __nv_bfloat16* Blo = wlo + (size_t)L * DIM * DIM;
        const float* bias = (L < 5) ? mlp_b + L * DIM : nullptr;
        int applySilu = (L < 4);
        float* ssAcc = (L == 4) ? ssp : nullptr;
        const float* ssScale = (L == 5) ? ssp : nullptr;

        // ---- dependency wait + stage-reuse safety barrier ----
        if (tid == 0) {
            volatile unsigned* wflag = &g_wcnt[L];
            while (*wflag < (unsigned)NWCTA) __nanosleep(64);
            if (L == 0) {
                volatile unsigned* e = &g_emb[mt];
                while (*e == 0u) __nanosleep(64);
            } else {
                volatile unsigned* f = &g_cnt[(L - 1) * NMT + mt];
                while (*f < 8u) __nanosleep(64);
            }
        }
        __syncthreads();   // also guarantees prior tile's smem reads are done

        float acc[4][4][4];
        #pragma unroll
        for (int i = 0; i < 4; ++i)
            #pragma unroll
            for (int j = 0; j < 4; ++j)
                #pragma unroll
                for (int q = 0; q < 4; ++q) acc[i][j][q] = 0.f;

        auto issue = [&](int j) {
            int k0 = j * 32;
            uint32_t st = dsm + (j % STAGES) * STAGE_BYTES;
            #pragma unroll
            for (int u = 0; u < 8; ++u) {
                int i = tid + u * 256;
                int tt = i >> 9, rr = (i >> 2) & 127, cc = i & 3;
                const __nv_bfloat16* gb;
                if (tt == 0)      gb = Ahi + (size_t)(bm + rr) * DIM;
                else if (tt == 1) gb = Alo + (size_t)(bm + rr) * DIM;
                else if (tt == 2) gb = Bhi + (size_t)(bn + rr) * DIM;
                else              gb = Blo + (size_t)(bn + rr) * DIM;
                uint32_t daddr = st + tt * TILE_BYTES + rr * 64 + (((cc ^ ((rr >> 1) & 3))) * 16);
                cp_async16(daddr, gb + k0 + cc * 8);
            }
            cp_commit();
        };

        issue(0); issue(1);

        for (int j = 0; j < NCHUNK; ++j) {
            if (j == NCHUNK - 1) { CP_WAIT(0); } else { CP_WAIT(1); }
            __syncthreads();
            if (j + 2 < NCHUNK) issue(j + 2);

            uint32_t st = dsm + (j % STAGES) * STAGE_BYTES;
            #pragma unroll
            for (int ks = 0; ks < 2; ++ks) {
                uint32_t a_off = ((a_c + ks * 2) ^ sw) * 16;
                uint32_t b_off = ((b_c + ks * 2) ^ sw) * 16;
                uint32_t ah[4][4], al[4][4], bh2[2][4], bl2[2][4];
                // pass-1 operands first: MMAs can start after 6 ldsm
                #pragma unroll
                for (int np = 0; np < 2; ++np) {
                    uint32_t rb = st + 2 * TILE_BYTES + (b_row + np * 16) * 64 + b_off;
                    ldsm4(rb, bh2[np][0], bh2[np][1], bh2[np][2], bh2[np][3]);
                }
                #pragma unroll
                for (int am = 0; am < 4; ++am) {
                    uint32_t ra = st + (a_row + am * 16) * 64 + a_off;
                    ldsm4(ra, ah[am][0], ah[am][1], ah[am][2], ah[am][3]);
                }
                #pragma unroll
                for (int am = 0; am < 4; ++am)
                    #pragma unroll
                    for (int an = 0; an < 4; ++an) {
                        uint32_t* bp = bh2[an >> 1];
                        mma_bf16(acc[am][an][0], acc[am][an][1], acc[am][an][2], acc[am][an][3],
                                 ah[am][0], ah[am][1], ah[am][2], ah[am][3],
                                 bp[(an & 1) * 2], bp[(an & 1) * 2 + 1]);
                    }
                #pragma unroll
                for (int am = 0; am < 4; ++am) {
                    uint32_t ra = st + TILE_BYTES + (a_row + am * 16) * 64 + a_off;
                    ldsm4(ra, al[am][0], al[am][1], al[am][2], al[am][3]);
                }
                #pragma unroll
                for (int am = 0; am < 4; ++am)
                    #pragma unroll
                    for (int an = 0; an < 4; ++an) {
                        uint32_t* bp = bh2[an >> 1];
                        mma_bf16(acc[am][an][0], acc[am][an][1], acc[am][an][2], acc[am][an][3],
                                 al[am][0], al[am][1], al[am][2], al[am][3],
                                 bp[(an & 1) * 2], bp[(an & 1) * 2 + 1]);
                    }
                #pragma unroll
                for (int np = 0; np < 2; ++np) {
                    uint32_t rb = st + 3 * TILE_BYTES + (b_row + np * 16) * 64 + b_off;
                    ldsm4(rb, bl2[np][0], bl2[np][1], bl2[np][2], bl2[np][3]);
                }
                #pragma unroll
                for (int am = 0; am < 4; ++am)
                    #pragma unroll
                    for (int an = 0; an < 4; ++an) {
                        uint32_t* bp = bl2[an >> 1];
                        mma_bf16(acc[am][an][0], acc[am][an][1], acc[am][an][2], acc[am][an][3],
                                 ah[am][0], ah[am][1], ah[am][2], ah[am][3],
                                 bp[(an & 1) * 2], bp[(an & 1) * 2 + 1]);
                    }
            }
        }

        // ---- epilogue ----
        float2 bv[4];
        #pragma unroll
        for (int an = 0; an < 4; ++an)
            bv[an] = bias ? *(const float2*)(bias + bn + wn * 32 + an * 8 + ec)
                          : make_float2(0.f, 0.f);

        #pragma unroll
        for (int am = 0; am < 4; ++am) {
            #pragma unroll
            for (int h = 0; h < 2; ++h) {
                int row = bm + wm * 64 + am * 16 + er + h * 8;
                float sc = 1.f;
                if (ssScale) {
                    float ssv = __ldg(ssScale + row);
                    float n = fmaxf(sqrtf(ssv), EPSF);
                    sc = atanhf(fminf(tanhf(n), MAXNORM)) / n;
                }
                float sspv = 0.f;
                #pragma unroll
                for (int an = 0; an < 4; ++an) {
                    int col = bn + wn * 32 + an * 8 + ec;
                    float v0 = acc[am][an][h * 2 + 0] + bv[an].x;
                    float v1 = acc[am][an][h * 2 + 1] + bv[an].y;
                    if (applySilu) {
                        v0 = v0 / (1.0f + __expf(-v0));
                        v1 = v1 / (1.0f + __expf(-v1));
                    }
                    if (ssAcc) sspv += v0 * v0 + v1 * v1;
                    v0 *= sc; v1 *= sc;
                    __nv_bfloat16 h0, l0, h1, l1;
                    split_bf16(v0, h0, l0);
                    split_bf16(v1, h1, l1);
                    __nv_bfloat16 hp[2] = {h0, h1}, lp[2] = {l0, l1};
                    *(uint32_t*)(Ohi + (size_t)row * DIM + col) = *(uint32_t*)hp;
                    *(uint32_t*)(Olo + (size_t)row * DIM + col) = *(uint32_t*)lp;
                }
                if (ssAcc) {
                    sspv += __shfl_xor_sync(0xffffffffu, sspv, 1);
                    sspv += __shfl_xor_sync(0xffffffffu, sspv, 2);
                    if ((lid & 3) == 0) atomicAdd(ssAcc + row, sspv);
                }
            }
        }

        // ---- publish completion ----
        __threadfence();
        __syncthreads();
        if (tid == 0) atomicAdd(&g_cnt[L * NMT + mt], 1u);
    }
}

// ===========================================================================
// block reduction over 256 threads
// ===========================================================================
__device__ __forceinline__ float block_reduce_sum_256(float v) {
    __shared__ float s[8];
    __syncthreads();
    int lane = threadIdx.x & 31, w = threadIdx.x >> 5;
    #pragma unroll
    for (int o = 16; o; o >>= 1) v += __shfl_down_sync(0xffffffffu, v, o);
    if (lane == 0) s[w] = v;
    __syncthreads();
    if (threadIdx.x == 0) {
        float t = 0.f;
        #pragma unroll
        for (int i = 0; i < 8; ++i) t += s[i];
        s[0] = t;
    }
    __syncthreads();
    return s[0];
}

// ===========================================================================
// Tensor-core aggregation: agg[b,c,d] = sum_r adj[r,c]*m[r,d] + bias[d].
// ===========================================================================
#define ASTR 88                               // elements; 176B row stride
#define AGG_SMEM ((80 + 2 * 128) * ASTR * 2)  // 59136 B

__global__ __launch_bounds__(128) void agg_mma_kernel(
    const __nv_bfloat16* __restrict__ mhi, const __nv_bfloat16* __restrict__ mlo,
    const int* __restrict__ edge, const float* __restrict__ bias,
    float* __restrict__ outF)
{
    extern __shared__ char agg_raw[];
    uint32_t sA  = smem_u32(agg_raw);           // adjT [80][88]
    uint32_t sBh = sA + 80 * ASTR * 2;          // m-hi [128][88]
    uint32_t sBl = sBh + 128 * ASTR * 2;        // m-lo [128][88]

    int d0 = blockIdx.x * 128;
    int b  = blockIdx.y;
    int tid = threadIdx.x, wid = tid >> 5, lid = tid & 31;

    for (int i = tid; i < AGG_SMEM / 4; i += 128)
        asm volatile("st.shared.b32 [%0], %1;" :: "r"(sA + i * 4), "r"(0) : "memory");
    __syncthreads();

    const int* eb = edge + (size_t)b * SEQ * SEQ;
    for (int i = tid; i < SEQ * SEQ; i += 128) {
        int r = i / SEQ, c = i % SEQ;
        unsigned short v = (eb[i] != 0) ? (unsigned short)0x3F80 : (unsigned short)0;
        asm volatile("st.shared.u16 [%0], %1;"
                     :: "r"(sA + (c * ASTR + r) * 2), "h"(v) : "memory");
    }

    const __nv_bfloat16* Mh = mhi + (size_t)b * SEQ * DIM + d0;
    const __nv_bfloat16* Ml = mlo + (size_t)b * SEQ * DIM + d0;
    for (int i = tid; i < SEQ * 64; i += 128) {
        int r = i / 64, dd2 = i % 64;
        uint32_t vh = *(const uint32_t*)(Mh + (size_t)r * DIM + dd2 * 2);
        uint32_t vl = *(const uint32_t*)(Ml + (size_t)r * DIM + dd2 * 2);
        uint32_t o0 = ((dd2 * 2) * ASTR + r) * 2;
        uint32_t o1 = ((dd2 * 2 + 1) * ASTR + r) * 2;
        asm volatile("st.shared.u16 [%0], %1;" :: "r"(sBh + o0), "h"((unsigned short)(vh & 0xffff)) : "memory");
        asm volatile("st.shared.u16 [%0], %1;" :: "r"(sBh + o1), "h"((unsigned short)(vh >> 16)) : "memory");
        asm volatile("st.shared.u16 [%0], %1;" :: "r"(sBl + o0), "h"((unsigned short)(vl & 0xffff)) : "memory");
        asm volatile("st.shared.u16 [%0], %1;" :: "r"(sBl + o1), "h"((unsigned short)(vl >> 16)) : "memory");
    }
    __syncthreads();

    int t8 = lid >> 3, l8 = lid & 7;
    float acc[5][4][4];
    #pragma unroll
    for (int mt = 0; mt < 5; ++mt)
        #pragma unroll
        for (int an = 0; an < 4; ++an)
            #pragma unroll
            for (int r = 0; r < 4; ++r) acc[mt][an][r] = 0.f;

    #pragma unroll
    for (int k = 0; k < 5; ++k) {
        uint32_t bh2[2][4], bl2[2][4], a[5][4];
        #pragma unroll
        for (int g = 0; g < 2; ++g) {
            uint32_t rb = (uint32_t)((wid * 32 + g * 16 + (t8 >> 1) * 8 + l8) * (ASTR * 2)
                                     + ((t8 & 1) + k * 2) * 16);
            ldsm4(sBh + rb, bh2[g][0], bh2[g][1], bh2[g][2], bh2[g][3]);
            ldsm4(sBl + rb, bl2[g][0], bl2[g][1], bl2[g][2], bl2[g][3]);
        }
        #pragma unroll
        for (int mt = 0; mt < 5; ++mt) {
            uint32_t ra = sA + (uint32_t)((mt * 16 + (t8 & 1) * 8 + l8) * (ASTR * 2)
                                          + ((t8 >> 1) + k * 2) * 16);
            ldsm4(ra, a[mt][0], a[mt][1], a[mt][2], a[mt][3]);
        }
        #pragma unroll
        for (int mt = 0; mt < 5; ++mt)
            #pragma unroll
            for (int an = 0; an < 4; ++an) {
                uint32_t* bp = bh2[an >> 1];
                mma_bf16(acc[mt][an][0], acc[mt][an][1], acc[mt][an][2], acc[mt][an][3],
                         a[mt][0], a[mt][1], a[mt][2], a[mt][3],
                         bp[(an & 1) * 2], bp[(an & 1) * 2 + 1]);
            }
        #pragma unroll
        for (int mt = 0; mt < 5; ++mt)
            #pragma unroll
            for (int an = 0; an < 4; ++an) {
                uint32_t* bp = bl2[an >> 1];
                mma_bf16(acc[mt][an][0], acc[mt][an][1], acc[mt][an][2], acc[mt][an][3],
                         a[mt][0], a[mt][1], a[mt][2], a[mt][3],
                         bp[(an & 1) * 2], bp[(an & 1) * 2 + 1]);
            }
    }

    int er = lid >> 2, ec = (lid & 3) * 2;
    float2 bv[4];
    #pragma unroll
    for (int an = 0; an < 4; ++an)
        bv[an] = *(const float2*)(bias + d0 + wid * 32 + an * 8 + ec);

    #pragma unroll
    for (int mt = 0; mt < 5; ++mt) {
        #pragma unroll
        for (int h = 0; h < 2; ++h) {
            int c = mt * 16 + er + h * 8;
            if (c < SEQ) {
                #pragma unroll
                for (int an = 0; an < 4; ++an) {
                    int d = d0 + wid * 32 + an * 8 + ec;
                    float2 o;
                    o.x = acc[mt][an][h * 2 + 0] + bv[an].x;
                    o.y = acc[mt][an][h * 2 + 1] + bv[an].y;
                    *(float2*)(outF + ((size_t)b * SEQ + c) * DIM + d) = o;
                }
            }
        }
    }
}

// ===========================================================================
// out = logmap0(expmap0(leaky_relu(logmap0(expmap0(agg)))))
// ===========================================================================
__global__ void final_kernel(const float* __restrict__ in, float* __restrict__ out) {
    size_t base = (size_t)blockIdx.x * DIM;
    float4 v = ((const float4*)(in + base))[threadIdx.x];
    float ss = v.x * v.x + v.y * v.y + v.z * v.z + v.w * v.w;
    float sum = block_reduce_sum_256(ss);
    float n1 = fmaxf(sqrtf(sum), EPSF);
    float sc1 = atanhf(fminf(tanhf(n1), MAXNORM)) / n1;

    float u0 = sc1 * v.x; u0 = (u0 > 0.f) ? u0 : 0.01f * u0;
    float u1 = sc1 * v.y; u1 = (u1 > 0.f) ? u1 : 0.01f * u1;
    float u2 = sc1 * v.z; u2 = (u2 > 0.f) ? u2 : 0.01f * u2;
    float u3 = sc1 * v.w; u3 = (u3 > 0.f) ? u3 : 0.01f * u3;

    float ss2 = u0 * u0 + u1 * u1 + u2 * u2 + u3 * u3;
    float sum2 = block_reduce_sum_256(ss2);
    float n2 = fmaxf(sqrtf(sum2), EPSF);
    float sc2 = atanhf(fminf(tanhf(n2), MAXNORM)) / n2;

    float4 o;
    o.x = sc2 * u0; o.y = sc2 * u1; o.z = sc2 * u2; o.w = sc2 * u3;
    ((float4*)(out + base))[threadIdx.x] = o;
}

// ===========================================================================
extern "C" void kernel_launch(void* const* d_in, const int* in_sizes, int n_in,
                              void* d_out, int out_size) {
    const void*  tokens = d_in[0];
    const int*   edge   = (const int*)d_in[1];
    const float* tok_w  = (const float*)d_in[2];
    const float* pos_w  = (const float*)d_in[3];
    const float* mlp_w  = (const float*)d_in[4];
    const float* mlp_b  = (const float*)d_in[5];
    const float* gcn_w  = (const float*)d_in[6];
    const float* gcn_b  = (const float*)d_in[7];
    float* out = (float*)d_out;

    __nv_bfloat16 *ahi, *alo, *bhi, *blo, *whi, *wlo;
    float *bufF, *ssp;
    cudaGetSymbolAddress((void**)&ahi, g_ahi);
    cudaGetSymbolAddress((void**)&alo, g_alo);
    cudaGetSymbolAddress((void**)&bhi, g_bhi);
    cudaGetSymbolAddress((void**)&blo, g_blo);
    cudaGetSymbolAddress((void**)&whi, g_whi);
    cudaGetSymbolAddress((void**)&wlo, g_wlo);
    cudaGetSymbolAddress((void**)&bufF, g_bufF);
    cudaGetSymbolAddress((void**)&ssp, g_ss);

    cudaFuncSetAttribute(mega_gemm_kernel,
                         cudaFuncAttributeMaxDynamicSharedMemorySize, DSM_BYTES);
    cudaFuncSetAttribute(agg_mma_kernel,
                         cudaFuncAttributeMaxDynamicSharedMemorySize, AGG_SMEM);

    detect_tok_kernel<<<1, 256>>>((const unsigned long long*)tokens, NROWS / 2);

    // Phase 0 (embed + weight split) fused into the persistent GEMM kernel.
    mega_gemm_kernel<<<NCTA, 256, DSM_BYTES>>>(tokens, tok_w, pos_w, mlp_w, gcn_w,
                                               ahi, alo, bhi, blo, whi, wlo,
                                               mlp_b, ssp);

    agg_mma_kernel<<<dim3(DIM / 128, BATCH), 128, AGG_SMEM>>>(ahi, alo, edge,
                                                              gcn_b + 3 * DIM, bufF);

    final_kernel<<<NROWS, 256>>>(bufF, out);
}